// round 1
// baseline (speedup 1.0000x reference)
#include <cuda_runtime.h>
#include <math.h>

// ---------------- static scratch (no allocations allowed) ----------------
__device__ float g_q[2048 * 2048];   // Q projection  (B*T=2048, C=2048)
__device__ float g_y[2048 * 2048];   // attention out (B*T, C)
__device__ float g_k[512 * 512];     // kproj (B*N*K=512, n_kv*D=512)
__device__ float g_v[512 * 512];     // vproj

// ---------------- 128x128x8 register-blocked SGEMM -----------------------
// C[M,N] = A[M,K] * B[K,N], all row-major, dims divisible by 128 (M,N) and 8 (K).
// 256 threads, each computes an 8x8 microtile. Optional tanh(gate) epilogue.
template <bool GATED>
__global__ void __launch_bounds__(256)
sgemm128(const float* __restrict__ A, const float* __restrict__ B,
         float* __restrict__ C, int M, int N, int K,
         const float* __restrict__ gate) {
    constexpr int BM = 128, BN = 128, BK = 8;
    __shared__ float As[BK][BM];
    __shared__ float Bs[BK][BN];

    const int tid = threadIdx.x;
    const int row0 = blockIdx.y * BM;
    const int col0 = blockIdx.x * BN;

    // A tile loads: 128 rows x 8 k = 256 float4 (2 per row)
    const int a_row = tid >> 1;
    const int a_col = (tid & 1) * 4;
    // B tile loads: 8 rows x 128 cols = 256 float4 (32 per row)
    const int b_row = tid >> 5;
    const int b_col = (tid & 31) * 4;

    const int tx = tid & 15;   // col microtile
    const int ty = tid >> 4;   // row microtile

    float acc[8][8];
#pragma unroll
    for (int i = 0; i < 8; i++)
#pragma unroll
        for (int j = 0; j < 8; j++) acc[i][j] = 0.0f;

    const float* Aptr = A + (size_t)(row0 + a_row) * K + a_col;
    const float* Bptr = B + (size_t)b_row * N + col0 + b_col;

    for (int k0 = 0; k0 < K; k0 += BK) {
        float4 av = *(const float4*)(Aptr + k0);
        As[a_col + 0][a_row] = av.x;
        As[a_col + 1][a_row] = av.y;
        As[a_col + 2][a_row] = av.z;
        As[a_col + 3][a_row] = av.w;
        float4 bv = *(const float4*)(Bptr + (size_t)k0 * N);
        *(float4*)&Bs[b_row][b_col] = bv;
        __syncthreads();

#pragma unroll
        for (int k = 0; k < BK; k++) {
            float ar[8], br[8];
#pragma unroll
            for (int i = 0; i < 8; i++) ar[i] = As[k][ty * 8 + i];
#pragma unroll
            for (int j = 0; j < 8; j++) br[j] = Bs[k][tx * 8 + j];
#pragma unroll
            for (int i = 0; i < 8; i++)
#pragma unroll
                for (int j = 0; j < 8; j++) acc[i][j] += ar[i] * br[j];
        }
        __syncthreads();
    }

    float scale = 1.0f;
    if (GATED) scale = tanhf(gate[0]);

#pragma unroll
    for (int i = 0; i < 8; i++) {
        float* crow = C + (size_t)(row0 + ty * 8 + i) * N + col0 + tx * 8;
#pragma unroll
        for (int j = 0; j < 8; j += 4) {
            float4 v;
            v.x = acc[i][j + 0] * scale;
            v.y = acc[i][j + 1] * scale;
            v.z = acc[i][j + 2] * scale;
            v.w = acc[i][j + 3] * scale;
            *(float4*)(crow + j) = v;
        }
    }
}

// ---------------- tiny-K attention ---------------------------------------
// One block per (token bt, kv-group g). 4 warps = 4 rep-heads.
// kproj/vproj rows for the selected channel are staged in padded smem.
__global__ void __launch_bounds__(128)
attn_kernel(const float* __restrict__ q, const float* __restrict__ kproj,
            const float* __restrict__ vproj, const int* __restrict__ mask,
            float* __restrict__ y) {
    __shared__ float qs[4][128];
    __shared__ float ks[32][129];   // +1 pad: conflict-free row-per-lane reads
    __shared__ float vs[32][129];
    __shared__ float attn_s[4][32];

    const int bt = blockIdx.x;          // 0..2047  (b*1024 + t)
    const int g  = blockIdx.y;          // 0..3
    const int b  = bt >> 10;            // T = 1024
    const int tid  = threadIdx.x;       // 128
    const int lane = tid & 31;
    const int w    = tid >> 5;          // warp = rep index r

    const int ch = mask[bt];

    // load q for all 4 rep heads of this group
#pragma unroll
    for (int r = 0; r < 4; r++)
        qs[r][tid] = q[(size_t)bt * 2048 + g * 512 + r * 128 + tid];

    // load 32 k/v rows (each 128 floats) for (b, ch, g)
    const size_t kvbase = ((size_t)(b * 8 + ch) * 32) * 512 + g * 128;
#pragma unroll
    for (int i = 0; i < 8; i++) {
        int kk = w * 8 + i;
#pragma unroll
        for (int j = 0; j < 4; j++) {
            ks[kk][lane + 32 * j] = kproj[kvbase + (size_t)kk * 512 + lane + 32 * j];
            vs[kk][lane + 32 * j] = vproj[kvbase + (size_t)kk * 512 + lane + 32 * j];
        }
    }
    __syncthreads();

    const int r = w;
    // each lane computes the score for one key
    float score = 0.0f;
#pragma unroll
    for (int d = 0; d < 128; d++) score += qs[r][d] * ks[lane][d];
    score *= 0.08838834764831845f;  // 1/sqrt(128)

    // warp softmax over the 32 keys
    float m = score;
#pragma unroll
    for (int off = 16; off; off >>= 1) m = fmaxf(m, __shfl_xor_sync(0xFFFFFFFFu, m, off));
    float e = __expf(score - m);
    float s = e;
#pragma unroll
    for (int off = 16; off; off >>= 1) s += __shfl_xor_sync(0xFFFFFFFFu, s, off);
    attn_s[r][lane] = e / s;
    __syncwarp();

    // y[d] = sum_k attn[k] * v[k][d]; each lane handles 4 dims
    float acc[4] = {0.f, 0.f, 0.f, 0.f};
#pragma unroll
    for (int kk = 0; kk < 32; kk++) {
        float a = attn_s[r][kk];
#pragma unroll
        for (int j = 0; j < 4; j++) acc[j] += a * vs[kk][lane + 32 * j];
    }
#pragma unroll
    for (int j = 0; j < 4; j++)
        y[(size_t)bt * 2048 + g * 512 + r * 128 + lane + 32 * j] = acc[j];
}

// ---------------- launch ---------------------------------------------------
extern "C" void kernel_launch(void* const* d_in, const int* in_sizes, int n_in,
                              void* d_out, int out_size) {
    const float* x    = (const float*)d_in[0];   // (B,T,C) = (2,1024,2048)
    const float* cst  = (const float*)d_in[1];   // (B,N,K,C) = (2,8,32,2048)
    const int*   mask = (const int*)d_in[2];     // (B,T)
    const float* Wq   = (const float*)d_in[3];   // (2048, 2048)
    const float* Wk   = (const float*)d_in[4];   // (2048, 512)
    const float* Wv   = (const float*)d_in[5];   // (2048, 512)
    const float* Wo   = (const float*)d_in[6];   // (2048, 2048)
    const float* gate = (const float*)d_in[7];   // (1,)
    float* out = (float*)d_out;                  // (B,T,C)

    float *qb, *yb, *kb, *vb;
    cudaGetSymbolAddress((void**)&qb, g_q);
    cudaGetSymbolAddress((void**)&yb, g_y);
    cudaGetSymbolAddress((void**)&kb, g_k);
    cudaGetSymbolAddress((void**)&vb, g_v);

    // 1) Q projection: (2048,2048) = x @ Wq
    sgemm128<false><<<dim3(16, 16), 256>>>(x, Wq, qb, 2048, 2048, 2048, nullptr);
    // 2) channel latent projections: (512,512) = cst @ Wk / Wv
    sgemm128<false><<<dim3(4, 4), 256>>>(cst, Wk, kb, 512, 512, 2048, nullptr);
    sgemm128<false><<<dim3(4, 4), 256>>>(cst, Wv, vb, 512, 512, 2048, nullptr);
    // 3) gather + tiny-K GQA attention
    attn_kernel<<<dim3(2048, 4), 128>>>(qb, kb, vb, mask, yb);
    // 4) output projection with tanh(gate) epilogue
    sgemm128<true><<<dim3(16, 16), 256>>>(yb, Wo, out, 2048, 2048, 2048, gate);
}

// round 3
// speedup vs baseline: 2.0760x; 2.0760x over previous
#include <cuda_runtime.h>
#include <math.h>
#include <stdint.h>
#include <mma.h>

using namespace nvcuda;

// ===================== static scratch (no allocs allowed) ====================
__device__ float g_q[2048 * 2048];   // Q projection  (B*T=2048, C=2048)
__device__ float g_y[2048 * 2048];   // attention out (B*T, C)
__device__ float g_k[512 * 512];     // kproj (B*N*K=512, n_kv*D=512)
__device__ float g_v[512 * 512];     // vproj

__device__ __forceinline__ float to_tf32(float x) {
    asm("cvt.rna.tf32.f32 %0, %0;" : "+f"(x));
    return x;
}

// ===================== wmma tf32 GEMM body ==================================
// C[M,N] = A[M,K] @ B[K,N], all row-major fp32. BK=32 fixed.
// Double-buffered smem, register prefetch, m16n16k8 tf32 fragments.
template <int BM, int BN, int WM, int WN, bool GATED>
__device__ __forceinline__ void gemm_body(
    const float* __restrict__ A, const float* __restrict__ B,
    float* __restrict__ C, int M, int N, int K,
    const float* __restrict__ gate, int bx, int by, char* smem_raw) {
    constexpr int BK = 32;
    constexpr int WARPS_M = BM / WM;
    constexpr int WARPS_N = BN / WN;
    constexpr int NT = WARPS_M * WARPS_N * 32;
    constexpr int LDA = BK + 4;   // padded pitches (floats)
    constexpr int LDB = BN + 4;
    constexpr int A_ST = BM * LDA;
    constexpr int B_ST = BK * LDB;
    constexpr int A_IT = (BM * BK / 4) / NT;  // float4 per thread
    constexpr int B_IT = (BK * BN / 4) / NT;
    constexpr int MF = WM / 16;   // a-frags per warp
    constexpr int NF = WN / 16;   // b-frags per warp

    float* As = (float*)smem_raw;           // [2][A_ST]
    float* Bs = As + 2 * A_ST;              // [2][B_ST]

    const int tid = threadIdx.x;
    const int wid = tid >> 5;
    const int wm0 = (wid / WARPS_N) * WM;
    const int wn0 = (wid % WARPS_N) * WN;
    const int row0 = by * BM;
    const int col0 = bx * BN;

    wmma::fragment<wmma::accumulator, 16, 16, 8, float> acc[MF][NF];
#pragma unroll
    for (int i = 0; i < MF; i++)
#pragma unroll
        for (int j = 0; j < NF; j++) wmma::fill_fragment(acc[i][j], 0.0f);

    float4 ra[A_IT], rb[B_IT];

    const int NIT = K / BK;

    // ---- global load of iteration `it` into registers ----
    auto g_load = [&](int it) {
        const int k0 = it * BK;
#pragma unroll
        for (int p = 0; p < A_IT; p++) {
            int f4 = tid + p * NT;
            int r = f4 >> 3, q = f4 & 7;            // 8 float4 per A row
            ra[p] = *(const float4*)(A + (size_t)(row0 + r) * K + k0 + q * 4);
        }
#pragma unroll
        for (int p = 0; p < B_IT; p++) {
            int f4 = tid + p * NT;
            int r = f4 / (BN / 4), q = f4 % (BN / 4);
            rb[p] = *(const float4*)(B + (size_t)(k0 + r) * N + col0 + q * 4);
        }
    };
    // ---- store registers (tf32-rounded) into smem stage s ----
    auto s_store = [&](int s) {
#pragma unroll
        for (int p = 0; p < A_IT; p++) {
            int f4 = tid + p * NT;
            int r = f4 >> 3, q = f4 & 7;
            float4 v = ra[p];
            v.x = to_tf32(v.x); v.y = to_tf32(v.y);
            v.z = to_tf32(v.z); v.w = to_tf32(v.w);
            *(float4*)(As + s * A_ST + r * LDA + q * 4) = v;
        }
#pragma unroll
        for (int p = 0; p < B_IT; p++) {
            int f4 = tid + p * NT;
            int r = f4 / (BN / 4), q = f4 % (BN / 4);
            float4 v = rb[p];
            v.x = to_tf32(v.x); v.y = to_tf32(v.y);
            v.z = to_tf32(v.z); v.w = to_tf32(v.w);
            *(float4*)(Bs + s * B_ST + r * LDB + q * 4) = v;
        }
    };

    g_load(0);
    s_store(0);
    __syncthreads();

    for (int it = 0; it < NIT; ++it) {
        const int s = it & 1;
        if (it + 1 < NIT) g_load(it + 1);

#pragma unroll
        for (int ks = 0; ks < BK / 8; ks++) {
            wmma::fragment<wmma::matrix_a, 16, 16, 8, wmma::precision::tf32,
                           wmma::row_major> af[MF];
            wmma::fragment<wmma::matrix_b, 16, 16, 8, wmma::precision::tf32,
                           wmma::row_major> bf[NF];
#pragma unroll
            for (int i = 0; i < MF; i++)
                wmma::load_matrix_sync(
                    af[i], As + s * A_ST + (wm0 + i * 16) * LDA + ks * 8, LDA);
#pragma unroll
            for (int j = 0; j < NF; j++)
                wmma::load_matrix_sync(
                    bf[j], Bs + s * B_ST + (ks * 8) * LDB + wn0 + j * 16, LDB);
#pragma unroll
            for (int i = 0; i < MF; i++)
#pragma unroll
                for (int j = 0; j < NF; j++)
                    wmma::mma_sync(acc[i][j], af[i], bf[j], acc[i][j]);
        }

        if (it + 1 < NIT) {
            s_store((it + 1) & 1);
            __syncthreads();
        }
    }

    float g = 1.0f;
    if (GATED) g = tanhf(gate[0]);
#pragma unroll
    for (int i = 0; i < MF; i++)
#pragma unroll
        for (int j = 0; j < NF; j++) {
            if (GATED) {
#pragma unroll
                for (int e = 0; e < acc[i][j].num_elements; e++)
                    acc[i][j].x[e] *= g;
            }
            wmma::store_matrix_sync(
                C + (size_t)(row0 + wm0 + i * 16) * N + col0 + wn0 + j * 16,
                acc[i][j], N, wmma::mem_row_major);
        }
}

// ===================== GEMM kernels =========================================
template <int BM, int BN, int WM, int WN, bool GATED>
__global__ void __launch_bounds__((BM / WM) * (BN / WN) * 32)
gemm_kernel(const float* __restrict__ A, const float* __restrict__ B,
            float* __restrict__ C, int M, int N, int K,
            const float* __restrict__ gate) {
    extern __shared__ char smem[];
    gemm_body<BM, BN, WM, WN, GATED>(A, B, C, M, N, K, gate,
                                     blockIdx.x, blockIdx.y, smem);
}

// fused kproj/vproj: blockIdx.z selects (Wk -> g_k) or (Wv -> g_v)
template <int BM, int BN, int WM, int WN>
__global__ void __launch_bounds__((BM / WM) * (BN / WN) * 32)
kv_gemm_kernel(const float* __restrict__ A, const float* __restrict__ Bk,
               const float* __restrict__ Bv, float* __restrict__ Ck,
               float* __restrict__ Cv, int M, int N, int K) {
    extern __shared__ char smem[];
    const float* B = blockIdx.z ? Bv : Bk;
    float* C = blockIdx.z ? Cv : Ck;
    gemm_body<BM, BN, WM, WN, false>(A, B, C, M, N, K, nullptr,
                                     blockIdx.x, blockIdx.y, smem);
}

// ===================== tiny-K attention =====================================
// One block per (token bt, kv-group g). 4 warps = 4 rep heads.
// Single kv smem buffer reused for K then V (halves smem -> ~2x occupancy).
__global__ void __launch_bounds__(128)
attn_kernel(const float* __restrict__ q, const float* __restrict__ kproj,
            const float* __restrict__ vproj, const int* __restrict__ mask,
            float* __restrict__ y) {
    __shared__ float qs[4][128];
    __shared__ float kv[32][129];
    __shared__ float attn_s[4][32];

    const int bt = blockIdx.x;
    const int g  = blockIdx.y;
    const int b  = bt >> 10;
    const int tid  = threadIdx.x;
    const int lane = tid & 31;
    const int w    = tid >> 5;

    const int ch = mask[bt];

#pragma unroll
    for (int r = 0; r < 4; r++)
        qs[r][tid] = q[(size_t)bt * 2048 + g * 512 + r * 128 + tid];

    const size_t kvbase = ((size_t)(b * 8 + ch) * 32) * 512 + g * 128;
    // stage K
#pragma unroll
    for (int i = 0; i < 8; i++) {
        int kk = w * 8 + i;
#pragma unroll
        for (int j = 0; j < 4; j++)
            kv[kk][lane + 32 * j] = kproj[kvbase + (size_t)kk * 512 + lane + 32 * j];
    }
    __syncthreads();

    const int r = w;
    float score = 0.0f;
#pragma unroll
    for (int d = 0; d < 128; d++) score += qs[r][d] * kv[lane][d];
    score *= 0.08838834764831845f;  // 1/sqrt(128)

    float m = score;
#pragma unroll
    for (int off = 16; off; off >>= 1) m = fmaxf(m, __shfl_xor_sync(0xFFFFFFFFu, m, off));
    float e = __expf(score - m);
    float s = e;
#pragma unroll
    for (int off = 16; off; off >>= 1) s += __shfl_xor_sync(0xFFFFFFFFu, s, off);
    attn_s[r][lane] = e / s;
    __syncthreads();

    // stage V into the same buffer
#pragma unroll
    for (int i = 0; i < 8; i++) {
        int kk = w * 8 + i;
#pragma unroll
        for (int j = 0; j < 4; j++)
            kv[kk][lane + 32 * j] = vproj[kvbase + (size_t)kk * 512 + lane + 32 * j];
    }
    __syncthreads();

    float acc[4] = {0.f, 0.f, 0.f, 0.f};
#pragma unroll
    for (int kk = 0; kk < 32; kk++) {
        float a = attn_s[r][kk];
#pragma unroll
        for (int j = 0; j < 4; j++) acc[j] += a * kv[kk][lane + 32 * j];
    }
#pragma unroll
    for (int j = 0; j < 4; j++)
        y[(size_t)bt * 2048 + g * 512 + r * 128 + lane + 32 * j] = acc[j];
}

// ===================== launch ===============================================
static constexpr int SMEM_BIG =
    (2 * 128 * 36 + 2 * 32 * 132) * 4;  // 70656 bytes (128x128 tile)
static constexpr int SMEM_KV =
    (2 * 64 * 36 + 2 * 32 * 68) * 4;    // 35840 bytes (64x64 tile)

extern "C" void kernel_launch(void* const* d_in, const int* in_sizes, int n_in,
                              void* d_out, int out_size) {
    const float* x    = (const float*)d_in[0];   // (2,1024,2048)
    const float* cst  = (const float*)d_in[1];   // (2,8,32,2048)
    const int*   mask = (const int*)d_in[2];     // (2,1024)
    const float* Wq   = (const float*)d_in[3];   // (2048, 2048)
    const float* Wk   = (const float*)d_in[4];   // (2048, 512)
    const float* Wv   = (const float*)d_in[5];   // (2048, 512)
    const float* Wo   = (const float*)d_in[6];   // (2048, 2048)
    const float* gate = (const float*)d_in[7];   // (1,)
    float* out = (float*)d_out;

    float *qb, *yb, *kb, *vb;
    cudaGetSymbolAddress((void**)&qb, g_q);
    cudaGetSymbolAddress((void**)&yb, g_y);
    cudaGetSymbolAddress((void**)&kb, g_k);
    cudaGetSymbolAddress((void**)&vb, g_v);

    cudaFuncSetAttribute(gemm_kernel<128, 128, 64, 32, false>,
                         cudaFuncAttributeMaxDynamicSharedMemorySize, SMEM_BIG);
    cudaFuncSetAttribute(gemm_kernel<128, 128, 64, 32, true>,
                         cudaFuncAttributeMaxDynamicSharedMemorySize, SMEM_BIG);
    cudaFuncSetAttribute(kv_gemm_kernel<64, 64, 32, 32>,
                         cudaFuncAttributeMaxDynamicSharedMemorySize, SMEM_KV);

    // 1) Q = x @ Wq : (2048 x 2048) @ (2048 x 2048)
    gemm_kernel<128, 128, 64, 32, false>
        <<<dim3(16, 16), 256, SMEM_BIG>>>(x, Wq, qb, 2048, 2048, 2048, nullptr);
    // 2) kproj / vproj = cst @ Wk / Wv : (512 x 2048) @ (2048 x 512), fused
    kv_gemm_kernel<64, 64, 32, 32>
        <<<dim3(8, 8, 2), 128, SMEM_KV>>>(cst, Wk, Wv, kb, vb, 512, 512, 2048);
    // 3) gather + tiny-K GQA attention
    attn_kernel<<<dim3(2048, 4), 128>>>(qb, kb, vb, mask, yb);
    // 4) out = (y @ Wo) * tanh(gate)
    gemm_kernel<128, 128, 64, 32, true>
        <<<dim3(16, 16), 256, SMEM_BIG>>>(yb, Wo, out, 2048, 2048, 2048, gate);
}

// round 4
// speedup vs baseline: 2.9466x; 1.4193x over previous
#include <cuda_runtime.h>
#include <math.h>
#include <stdint.h>
#include <mma.h>

using namespace nvcuda;

// ===================== static scratch (no allocs allowed) ====================
__device__ float g_q[2048 * 2048];   // Q projection  (B*T=2048, C=2048)
__device__ float g_y[2048 * 2048];   // attention out (B*T, C)
__device__ float g_k[512 * 512];     // kproj (B*N*K=512, n_kv*D=512)
__device__ float g_v[512 * 512];     // vproj

__device__ __forceinline__ float to_tf32(float x) {
    asm("cvt.rna.tf32.f32 %0, %0;" : "+f"(x));
    return x;
}
__device__ __forceinline__ uint32_t smem_u32(const void* p) {
    uint32_t a;
    asm("{ .reg .u64 t; cvta.to.shared.u64 t, %1; cvt.u32.u64 %0, t; }"
        : "=r"(a) : "l"(p));
    return a;
}
__device__ __forceinline__ void cp_async16(uint32_t dst, const void* src) {
    asm volatile("cp.async.cg.shared.global [%0], [%1], 16;" :: "r"(dst), "l"(src));
}
__device__ __forceinline__ void cp_commit() {
    asm volatile("cp.async.commit_group;" ::: "memory");
}
template <int N>
__device__ __forceinline__ void cp_wait() {
    asm volatile("cp.async.wait_group %0;" :: "n"(N) : "memory");
}

// ===================== cp.async tf32 GEMM body ==============================
// C[M,N] = A[M,K] @ B[K,N], row-major fp32 (values rounded to tf32 at frag load).
// BM=128, BN=256, BK=32, 512 threads (16 warps as 4x4, warp tile 32x64),
// 3-stage cp.async pipeline.
constexpr int BM = 128, BN = 256, BK = 32, STAGES = 3, NTHREADS = 512;
constexpr int LDA = BK + 4;                 // 36 floats (16B-aligned pitch)
constexpr int LDB = BN + 4;                 // 260 floats
constexpr int A_BYTES = BM * LDA * 4;       // 18432
constexpr int B_BYTES = BK * LDB * 4;       // 33280
constexpr int STAGE_BYTES = A_BYTES + B_BYTES;  // 51712
constexpr int GEMM_SMEM = STAGES * STAGE_BYTES; // 155136

template <bool GATED>
__device__ __forceinline__ void gemm_body(
    const float* __restrict__ A, const float* __restrict__ B,
    float* __restrict__ C, int N, int K,
    const float* __restrict__ gate, int bx, int by, char* smem) {
    const uint32_t sb = smem_u32(smem);
    const int tid = threadIdx.x;
    const int wid = tid >> 5;
    const int wm0 = (wid >> 2) * 32;   // 4 warp rows
    const int wn0 = (wid & 3) * 64;    // 4 warp cols
    const int row0 = by * BM;
    const int col0 = bx * BN;
    const int NIT = K / BK;

    // per-thread cp.async assignments
    // A: 1024 float4/stage -> 2 per thread; B: 2048 -> 4 per thread
    const int a_r0 = tid >> 3, a_q = (tid & 7) * 16;            // +512 -> +64 rows
    const int b_r0 = tid >> 6, b_q = (tid & 63) * 16;           // +512 -> +8 rows

    auto issue = [&](int it) {
        const int s = it % STAGES;
        const int k0 = it * BK;
        const uint32_t As = sb + s * STAGE_BYTES;
        const uint32_t Bs = As + A_BYTES;
#pragma unroll
        for (int p = 0; p < 2; p++) {
            int r = a_r0 + p * 64;
            cp_async16(As + r * (LDA * 4) + a_q,
                       A + (size_t)(row0 + r) * K + k0 + (a_q >> 2));
        }
#pragma unroll
        for (int p = 0; p < 4; p++) {
            int r = b_r0 + p * 8;
            cp_async16(Bs + r * (LDB * 4) + b_q,
                       B + (size_t)(k0 + r) * N + col0 + (b_q >> 2));
        }
    };

    wmma::fragment<wmma::accumulator, 16, 16, 8, float> acc[2][4];
#pragma unroll
    for (int i = 0; i < 2; i++)
#pragma unroll
        for (int j = 0; j < 4; j++) wmma::fill_fragment(acc[i][j], 0.0f);

#pragma unroll
    for (int s = 0; s < STAGES - 1; s++) {
        issue(s);
        cp_commit();
    }

    for (int it = 0; it < NIT; ++it) {
        cp_wait<STAGES - 2>();
        __syncthreads();

        const int s = it % STAGES;
        float* As = (float*)(smem + s * STAGE_BYTES);
        float* Bs = (float*)(smem + s * STAGE_BYTES + A_BYTES);

#pragma unroll
        for (int ks = 0; ks < BK / 8; ks++) {
            wmma::fragment<wmma::matrix_a, 16, 16, 8, wmma::precision::tf32,
                           wmma::row_major> af[2];
            wmma::fragment<wmma::matrix_b, 16, 16, 8, wmma::precision::tf32,
                           wmma::row_major> bf[4];
#pragma unroll
            for (int i = 0; i < 2; i++) {
                wmma::load_matrix_sync(af[i], As + (wm0 + i * 16) * LDA + ks * 8, LDA);
#pragma unroll
                for (int e = 0; e < af[i].num_elements; e++)
                    af[i].x[e] = to_tf32(af[i].x[e]);
            }
#pragma unroll
            for (int j = 0; j < 4; j++) {
                wmma::load_matrix_sync(bf[j], Bs + (ks * 8) * LDB + wn0 + j * 16, LDB);
#pragma unroll
                for (int e = 0; e < bf[j].num_elements; e++)
                    bf[j].x[e] = to_tf32(bf[j].x[e]);
            }
#pragma unroll
            for (int i = 0; i < 2; i++)
#pragma unroll
                for (int j = 0; j < 4; j++)
                    wmma::mma_sync(acc[i][j], af[i], bf[j], acc[i][j]);
        }

        if (it + STAGES - 1 < NIT) issue(it + STAGES - 1);
        cp_commit();
    }

    float g = 1.0f;
    if (GATED) g = tanhf(gate[0]);
#pragma unroll
    for (int i = 0; i < 2; i++)
#pragma unroll
        for (int j = 0; j < 4; j++) {
            if (GATED) {
#pragma unroll
                for (int e = 0; e < acc[i][j].num_elements; e++)
                    acc[i][j].x[e] *= g;
            }
            wmma::store_matrix_sync(
                C + (size_t)(row0 + wm0 + i * 16) * N + col0 + wn0 + j * 16,
                acc[i][j], N, wmma::mem_row_major);
        }
}

// ===================== stage 1: fused Q + kproj + vproj =====================
// 144 CTAs, single wave: bid<128 -> Q tiles; else kproj/vproj tiles.
__global__ void __launch_bounds__(NTHREADS, 1)
fused_gemm1(const float* __restrict__ x, const float* __restrict__ cst,
            const float* __restrict__ Wq, const float* __restrict__ Wk,
            const float* __restrict__ Wv, float* __restrict__ qb,
            float* __restrict__ kb, float* __restrict__ vb) {
    extern __shared__ char smem[];
    int bid = blockIdx.x;
    if (bid < 128) {
        gemm_body<false>(x, Wq, qb, 2048, 2048, nullptr, bid & 7, bid >> 3, smem);
    } else {
        int t = bid - 128;            // 0..15
        int w = t >> 3;               // 0: K, 1: V
        t &= 7;                       // 8 tiles: 4 row x 2 col
        gemm_body<false>(cst, w ? Wv : Wk, w ? vb : kb, 512, 2048, nullptr,
                         t & 1, t >> 1, smem);
    }
}

// ===================== stage 4: output projection ===========================
__global__ void __launch_bounds__(NTHREADS, 1)
out_gemm(const float* __restrict__ y, const float* __restrict__ Wo,
         float* __restrict__ out, const float* __restrict__ gate) {
    extern __shared__ char smem[];
    gemm_body<true>(y, Wo, out, 2048, 2048, gate, blockIdx.x & 7,
                    blockIdx.x >> 3, smem);
}

// ===================== tiny-K attention =====================================
__global__ void __launch_bounds__(128)
attn_kernel(const float* __restrict__ q, const float* __restrict__ kproj,
            const float* __restrict__ vproj, const int* __restrict__ mask,
            float* __restrict__ y) {
    __shared__ float qs[4][128];
    __shared__ float kv[32][129];
    __shared__ float attn_s[4][32];

    const int bt = blockIdx.x;
    const int g  = blockIdx.y;
    const int b  = bt >> 10;
    const int tid  = threadIdx.x;
    const int lane = tid & 31;
    const int w    = tid >> 5;

    const int ch = mask[bt];

#pragma unroll
    for (int r = 0; r < 4; r++)
        qs[r][tid] = q[(size_t)bt * 2048 + g * 512 + r * 128 + tid];

    const size_t kvbase = ((size_t)(b * 8 + ch) * 32) * 512 + g * 128;
#pragma unroll
    for (int i = 0; i < 8; i++) {
        int kk = w * 8 + i;
#pragma unroll
        for (int j = 0; j < 4; j++)
            kv[kk][lane + 32 * j] = kproj[kvbase + (size_t)kk * 512 + lane + 32 * j];
    }
    __syncthreads();

    const int r = w;
    float score = 0.0f;
#pragma unroll
    for (int d = 0; d < 128; d++) score += qs[r][d] * kv[lane][d];
    score *= 0.08838834764831845f;  // 1/sqrt(128)

    float m = score;
#pragma unroll
    for (int off = 16; off; off >>= 1) m = fmaxf(m, __shfl_xor_sync(0xFFFFFFFFu, m, off));
    float e = __expf(score - m);
    float s = e;
#pragma unroll
    for (int off = 16; off; off >>= 1) s += __shfl_xor_sync(0xFFFFFFFFu, s, off);
    attn_s[r][lane] = e / s;
    __syncthreads();

#pragma unroll
    for (int i = 0; i < 8; i++) {
        int kk = w * 8 + i;
#pragma unroll
        for (int j = 0; j < 4; j++)
            kv[kk][lane + 32 * j] = vproj[kvbase + (size_t)kk * 512 + lane + 32 * j];
    }
    __syncthreads();

    float acc[4] = {0.f, 0.f, 0.f, 0.f};
#pragma unroll
    for (int kk = 0; kk < 32; kk++) {
        float a = attn_s[r][kk];
#pragma unroll
        for (int j = 0; j < 4; j++) acc[j] += a * kv[kk][lane + 32 * j];
    }
#pragma unroll
    for (int j = 0; j < 4; j++)
        y[(size_t)bt * 2048 + g * 512 + r * 128 + lane + 32 * j] = acc[j];
}

// ===================== launch ===============================================
extern "C" void kernel_launch(void* const* d_in, const int* in_sizes, int n_in,
                              void* d_out, int out_size) {
    const float* x    = (const float*)d_in[0];   // (2,1024,2048)
    const float* cst  = (const float*)d_in[1];   // (2,8,32,2048)
    const int*   mask = (const int*)d_in[2];     // (2,1024)
    const float* Wq   = (const float*)d_in[3];   // (2048, 2048)
    const float* Wk   = (const float*)d_in[4];   // (2048, 512)
    const float* Wv   = (const float*)d_in[5];   // (2048, 512)
    const float* Wo   = (const float*)d_in[6];   // (2048, 2048)
    const float* gate = (const float*)d_in[7];   // (1,)
    float* out = (float*)d_out;

    float *qb, *yb, *kb, *vb;
    cudaGetSymbolAddress((void**)&qb, g_q);
    cudaGetSymbolAddress((void**)&yb, g_y);
    cudaGetSymbolAddress((void**)&kb, g_k);
    cudaGetSymbolAddress((void**)&vb, g_v);

    cudaFuncSetAttribute(fused_gemm1,
                         cudaFuncAttributeMaxDynamicSharedMemorySize, GEMM_SMEM);
    cudaFuncSetAttribute(out_gemm,
                         cudaFuncAttributeMaxDynamicSharedMemorySize, GEMM_SMEM);

    // 1+2) Q projection + kproj + vproj, one 144-CTA wave
    fused_gemm1<<<144, NTHREADS, GEMM_SMEM>>>(x, cst, Wq, Wk, Wv, qb, kb, vb);
    // 3) gather + tiny-K GQA attention
    attn_kernel<<<dim3(2048, 4), 128>>>(qb, kb, vb, mask, yb);
    // 4) out = (y @ Wo) * tanh(gate), 128-CTA wave
    out_gemm<<<128, NTHREADS, GEMM_SMEM>>>(yb, Wo, out, gate);
}

// round 5
// speedup vs baseline: 8.7337x; 2.9640x over previous
#include <cuda_runtime.h>
#include <cuda_fp16.h>
#include <math.h>
#include <stdint.h>
#include <mma.h>

using namespace nvcuda;

// ===================== static scratch (no allocs allowed) ====================
__device__ float  g_q[2048 * 2048];    // Q projection (fp32)
__device__ __half g_y[2048 * 2048];    // attention out (fp16, feeds out GEMM)
__device__ float  g_k[512 * 512];      // kproj fp32
__device__ float  g_v[512 * 512];      // vproj fp32
__device__ __half g_hx[2048 * 2048];   // x   in fp16
__device__ __half g_hcst[512 * 2048];  // cst in fp16
__device__ __half g_hwq[2048 * 2048];
__device__ __half g_hwk[2048 * 512];
__device__ __half g_hwv[2048 * 512];
__device__ __half g_hwo[2048 * 2048];

__device__ __forceinline__ uint32_t smem_u32(const void* p) {
    uint32_t a;
    asm("{ .reg .u64 t; cvta.to.shared.u64 t, %1; cvt.u32.u64 %0, t; }"
        : "=r"(a) : "l"(p));
    return a;
}
__device__ __forceinline__ void cp_async16(uint32_t dst, const void* src) {
    asm volatile("cp.async.cg.shared.global [%0], [%1], 16;" :: "r"(dst), "l"(src));
}
__device__ __forceinline__ void cp_commit() {
    asm volatile("cp.async.commit_group;" ::: "memory");
}
template <int N>
__device__ __forceinline__ void cp_wait() {
    asm volatile("cp.async.wait_group %0;" :: "n"(N) : "memory");
}

// ===================== fp32 -> fp16 conversion (all GEMM inputs) ============
// segments (elems): x 4194304 | cst 1048576 | Wq 4194304 | Wk 1048576 |
//                   Wv 1048576 | Wo 4194304   (total 15728640)
__global__ void __launch_bounds__(256)
cvt_all(const float* __restrict__ x, const float* __restrict__ cst,
        const float* __restrict__ wq, const float* __restrict__ wk,
        const float* __restrict__ wv, const float* __restrict__ wo,
        __half* __restrict__ hx, __half* __restrict__ hcst,
        __half* __restrict__ hwq, __half* __restrict__ hwk,
        __half* __restrict__ hwv, __half* __restrict__ hwo) {
    size_t i = ((size_t)blockIdx.x * blockDim.x + threadIdx.x) * 4;
    const float* src; __half* dst; size_t off;
    if      (i <  4194304u) { src = x;   dst = hx;   off = i; }
    else if (i <  5242880u) { src = cst; dst = hcst; off = i - 4194304u; }
    else if (i <  9437184u) { src = wq;  dst = hwq;  off = i - 5242880u; }
    else if (i < 10485760u) { src = wk;  dst = hwk;  off = i - 9437184u; }
    else if (i < 11534336u) { src = wv;  dst = hwv;  off = i - 10485760u; }
    else if (i < 15728640u) { src = wo;  dst = hwo;  off = i - 11534336u; }
    else return;
    float4 v = *(const float4*)(src + off);
    *(__half2*)(dst + off)     = __floats2half2_rn(v.x, v.y);
    *(__half2*)(dst + off + 2) = __floats2half2_rn(v.z, v.w);
}

// ===================== fp16 cp.async GEMM ===================================
// C[M,N](fp32) = A[M,K](fp16) @ B[K,N](fp16). BM=BN=128, BK=32, 256 threads
// (8 warps as 4x2, warp tile 32x64), 3-stage cp.async pipeline, 2 CTAs/SM.
constexpr int BK = 32, STAGES = 3;
constexpr int LDA = 40;    // halves (32 + 8 pad), 80B pitch
constexpr int LDB = 136;   // halves (128 + 8 pad), 272B pitch
constexpr int A_BYTES = 128 * LDA * 2;           // 10240
constexpr int B_BYTES = BK * LDB * 2;            // 8704
constexpr int STAGE_BYTES = A_BYTES + B_BYTES;   // 18944
constexpr int GEMM_SMEM = STAGES * STAGE_BYTES;  // 56832

template <bool GATED>
__device__ __forceinline__ void gemm_body(
    const __half* __restrict__ A, const __half* __restrict__ B,
    float* __restrict__ C, int N, int K,
    const float* __restrict__ gate, int bx, int by, char* smem) {
    const uint32_t sb = smem_u32(smem);
    const int tid = threadIdx.x;
    const int wid = tid >> 5;
    const int wm0 = (wid >> 1) * 32;   // 4 warp rows
    const int wn0 = (wid & 1) * 64;    // 2 warp cols
    const int row0 = by * 128;
    const int col0 = bx * 128;
    const int NIT = K / BK;

    // A: 128 rows x 64B -> 512 x 16B chunks, 2/thread
    const int a_r0 = tid >> 2, a_qb = (tid & 3) * 16;    // byte offset in row
    // B: 32 rows x 256B -> 512 x 16B chunks, 2/thread
    const int b_r0 = tid >> 4, b_qb = (tid & 15) * 16;

    auto issue = [&](int it) {
        const int s = it % STAGES;
        const int k0 = it * BK;
        const uint32_t As = sb + s * STAGE_BYTES;
        const uint32_t Bs = As + A_BYTES;
#pragma unroll
        for (int p = 0; p < 2; p++) {
            int r = a_r0 + p * 64;
            cp_async16(As + r * 80 + a_qb,
                       A + (size_t)(row0 + r) * K + k0 + (a_qb >> 1));
        }
#pragma unroll
        for (int p = 0; p < 2; p++) {
            int r = b_r0 + p * 16;
            cp_async16(Bs + r * 272 + b_qb,
                       B + (size_t)(k0 + r) * N + col0 + (b_qb >> 1));
        }
    };

    wmma::fragment<wmma::accumulator, 16, 16, 16, float> acc[2][4];
#pragma unroll
    for (int i = 0; i < 2; i++)
#pragma unroll
        for (int j = 0; j < 4; j++) wmma::fill_fragment(acc[i][j], 0.0f);

#pragma unroll
    for (int s = 0; s < STAGES - 1; s++) {
        issue(s);
        cp_commit();
    }

    for (int it = 0; it < NIT; ++it) {
        cp_wait<STAGES - 2>();
        __syncthreads();

        const int s = it % STAGES;
        const __half* Ah = (const __half*)(smem + s * STAGE_BYTES);
        const __half* Bh = (const __half*)(smem + s * STAGE_BYTES + A_BYTES);

#pragma unroll
        for (int ks = 0; ks < BK / 16; ks++) {
            wmma::fragment<wmma::matrix_a, 16, 16, 16, __half, wmma::row_major> af[2];
            wmma::fragment<wmma::matrix_b, 16, 16, 16, __half, wmma::row_major> bf[4];
#pragma unroll
            for (int i = 0; i < 2; i++)
                wmma::load_matrix_sync(af[i], Ah + (wm0 + i * 16) * LDA + ks * 16, LDA);
#pragma unroll
            for (int j = 0; j < 4; j++)
                wmma::load_matrix_sync(bf[j], Bh + (ks * 16) * LDB + wn0 + j * 16, LDB);
#pragma unroll
            for (int i = 0; i < 2; i++)
#pragma unroll
                for (int j = 0; j < 4; j++)
                    wmma::mma_sync(acc[i][j], af[i], bf[j], acc[i][j]);
        }

        if (it + STAGES - 1 < NIT) issue(it + STAGES - 1);
        cp_commit();
    }

    float g = 1.0f;
    if (GATED) g = tanhf(gate[0]);
#pragma unroll
    for (int i = 0; i < 2; i++)
#pragma unroll
        for (int j = 0; j < 4; j++) {
            if (GATED) {
#pragma unroll
                for (int e = 0; e < acc[i][j].num_elements; e++)
                    acc[i][j].x[e] *= g;
            }
            wmma::store_matrix_sync(
                C + (size_t)(row0 + wm0 + i * 16) * N + col0 + wn0 + j * 16,
                acc[i][j], N, wmma::mem_row_major);
        }
}

// stage 1: fused Q + kproj + vproj. 288 CTAs (256 Q + 16 K + 16 V), 2/SM.
__global__ void __launch_bounds__(256, 2)
fused_gemm1(const __half* __restrict__ hx, const __half* __restrict__ hcst,
            const __half* __restrict__ hwq, const __half* __restrict__ hwk,
            const __half* __restrict__ hwv, float* __restrict__ qb,
            float* __restrict__ kb, float* __restrict__ vb) {
    extern __shared__ char smem[];
    int bid = blockIdx.x;
    if (bid < 256) {
        gemm_body<false>(hx, hwq, qb, 2048, 2048, nullptr, bid & 15, bid >> 4, smem);
    } else {
        int t = bid - 256;            // 0..31
        int w = t >> 4;               // 0: K, 1: V
        t &= 15;                      // 4x4 tiles of 512x512
        gemm_body<false>(hcst, w ? hwv : hwk, w ? vb : kb, 512, 2048, nullptr,
                         t & 3, t >> 2, smem);
    }
}

// stage 4: out = (y @ Wo) * tanh(gate). 256 CTAs, 2/SM.
__global__ void __launch_bounds__(256, 2)
out_gemm(const __half* __restrict__ y, const __half* __restrict__ hwo,
         float* __restrict__ out, const float* __restrict__ gate) {
    extern __shared__ char smem[];
    gemm_body<true>(y, hwo, out, 2048, 2048, gate, blockIdx.x & 15,
                    blockIdx.x >> 4, smem);
}

// ===================== tiny-K attention (fp32 in, fp16 out) =================
__global__ void __launch_bounds__(128)
attn_kernel(const float* __restrict__ q, const float* __restrict__ kproj,
            const float* __restrict__ vproj, const int* __restrict__ mask,
            __half* __restrict__ y) {
    __shared__ float qs[4][128];
    __shared__ float kv[32][129];
    __shared__ float attn_s[4][32];

    const int bt = blockIdx.x;
    const int g  = blockIdx.y;
    const int b  = bt >> 10;
    const int tid  = threadIdx.x;
    const int lane = tid & 31;
    const int w    = tid >> 5;

    const int ch = mask[bt];

#pragma unroll
    for (int r = 0; r < 4; r++)
        qs[r][tid] = q[(size_t)bt * 2048 + g * 512 + r * 128 + tid];

    const size_t kvbase = ((size_t)(b * 8 + ch) * 32) * 512 + g * 128;
#pragma unroll
    for (int i = 0; i < 8; i++) {
        int kk = w * 8 + i;
#pragma unroll
        for (int j = 0; j < 4; j++)
            kv[kk][lane + 32 * j] = kproj[kvbase + (size_t)kk * 512 + lane + 32 * j];
    }
    __syncthreads();

    const int r = w;
    float score = 0.0f;
#pragma unroll
    for (int d = 0; d < 128; d++) score += qs[r][d] * kv[lane][d];
    score *= 0.08838834764831845f;  // 1/sqrt(128)

    float m = score;
#pragma unroll
    for (int off = 16; off; off >>= 1) m = fmaxf(m, __shfl_xor_sync(0xFFFFFFFFu, m, off));
    float e = __expf(score - m);
    float s = e;
#pragma unroll
    for (int off = 16; off; off >>= 1) s += __shfl_xor_sync(0xFFFFFFFFu, s, off);
    attn_s[r][lane] = e / s;
    __syncthreads();

#pragma unroll
    for (int i = 0; i < 8; i++) {
        int kk = w * 8 + i;
#pragma unroll
        for (int j = 0; j < 4; j++)
            kv[kk][lane + 32 * j] = vproj[kvbase + (size_t)kk * 512 + lane + 32 * j];
    }
    __syncthreads();

    float acc[4] = {0.f, 0.f, 0.f, 0.f};
#pragma unroll
    for (int kk = 0; kk < 32; kk++) {
        float a = attn_s[r][kk];
#pragma unroll
        for (int j = 0; j < 4; j++) acc[j] += a * kv[kk][lane + 32 * j];
    }
#pragma unroll
    for (int j = 0; j < 4; j++)
        y[(size_t)bt * 2048 + g * 512 + r * 128 + lane + 32 * j] =
            __float2half(acc[j]);
}

// ===================== launch ===============================================
extern "C" void kernel_launch(void* const* d_in, const int* in_sizes, int n_in,
                              void* d_out, int out_size) {
    const float* x    = (const float*)d_in[0];
    const float* cst  = (const float*)d_in[1];
    const int*   mask = (const int*)d_in[2];
    const float* Wq   = (const float*)d_in[3];
    const float* Wk   = (const float*)d_in[4];
    const float* Wv   = (const float*)d_in[5];
    const float* Wo   = (const float*)d_in[6];
    const float* gate = (const float*)d_in[7];
    float* out = (float*)d_out;

    float *qb, *kb, *vb;
    __half *yb, *hx, *hcst, *hwq, *hwk, *hwv, *hwo;
    cudaGetSymbolAddress((void**)&qb, g_q);
    cudaGetSymbolAddress((void**)&yb, g_y);
    cudaGetSymbolAddress((void**)&kb, g_k);
    cudaGetSymbolAddress((void**)&vb, g_v);
    cudaGetSymbolAddress((void**)&hx, g_hx);
    cudaGetSymbolAddress((void**)&hcst, g_hcst);
    cudaGetSymbolAddress((void**)&hwq, g_hwq);
    cudaGetSymbolAddress((void**)&hwk, g_hwk);
    cudaGetSymbolAddress((void**)&hwv, g_hwv);
    cudaGetSymbolAddress((void**)&hwo, g_hwo);

    cudaFuncSetAttribute(fused_gemm1,
                         cudaFuncAttributeMaxDynamicSharedMemorySize, GEMM_SMEM);
    cudaFuncSetAttribute(out_gemm,
                         cudaFuncAttributeMaxDynamicSharedMemorySize, GEMM_SMEM);

    // 0) convert all GEMM inputs to fp16 (15.7M elems, 4/thread)
    cvt_all<<<15360, 256>>>(x, cst, Wq, Wk, Wv, Wo, hx, hcst, hwq, hwk, hwv, hwo);
    // 1+2) Q projection + kproj + vproj, single wave at 2 CTAs/SM
    fused_gemm1<<<288, 256, GEMM_SMEM>>>(hx, hcst, hwq, hwk, hwv, qb, kb, vb);
    // 3) gather + tiny-K GQA attention (writes y as fp16)
    attn_kernel<<<dim3(2048, 4), 128>>>(qb, kb, vb, mask, yb);
    // 4) out = (y @ Wo) * tanh(gate)
    out_gemm<<<256, 256, GEMM_SMEM>>>(yb, hwo, out, gate);
}

// round 7
// speedup vs baseline: 9.5665x; 1.0954x over previous
#include <cuda_runtime.h>
#include <cuda_fp16.h>
#include <math.h>
#include <stdint.h>
#include <mma.h>

using namespace nvcuda;

// ===================== static scratch (no allocs allowed) ====================
__device__ float  g_q[2048 * 2048];    // Q projection (fp32)
__device__ __half g_y[2048 * 2048];    // attention out (fp16, feeds out GEMM)
__device__ __half g_k[512 * 512];      // kproj fp16
__device__ float  g_v[512 * 512];      // vproj fp32
__device__ __half g_hx[2048 * 2048];   // x   in fp16
__device__ __half g_hcst[512 * 2048];  // cst in fp16
__device__ __half g_hwq[2048 * 2048];
__device__ __half g_hwk[2048 * 512];
__device__ __half g_hwv[2048 * 512];
__device__ __half g_hwo[2048 * 2048];

__device__ __forceinline__ uint32_t smem_u32(const void* p) {
    uint32_t a;
    asm("{ .reg .u64 t; cvta.to.shared.u64 t, %1; cvt.u32.u64 %0, t; }"
        : "=r"(a) : "l"(p));
    return a;
}
__device__ __forceinline__ void cp_async16(uint32_t dst, const void* src) {
    asm volatile("cp.async.cg.shared.global [%0], [%1], 16;" :: "r"(dst), "l"(src));
}
__device__ __forceinline__ void cp_commit() {
    asm volatile("cp.async.commit_group;" ::: "memory");
}
template <int N>
__device__ __forceinline__ void cp_wait() {
    asm volatile("cp.async.wait_group %0;" :: "n"(N) : "memory");
}

// ===================== fp32 -> fp16 conversion (all GEMM inputs) ============
__global__ void __launch_bounds__(256)
cvt_all(const float* __restrict__ x, const float* __restrict__ cst,
        const float* __restrict__ wq, const float* __restrict__ wk,
        const float* __restrict__ wv, const float* __restrict__ wo,
        __half* __restrict__ hx, __half* __restrict__ hcst,
        __half* __restrict__ hwq, __half* __restrict__ hwk,
        __half* __restrict__ hwv, __half* __restrict__ hwo) {
    size_t i = ((size_t)blockIdx.x * blockDim.x + threadIdx.x) * 4;
    const float* src; __half* dst; size_t off;
    if      (i <  4194304u) { src = x;   dst = hx;   off = i; }
    else if (i <  5242880u) { src = cst; dst = hcst; off = i - 4194304u; }
    else if (i <  9437184u) { src = wq;  dst = hwq;  off = i - 5242880u; }
    else if (i < 10485760u) { src = wk;  dst = hwk;  off = i - 9437184u; }
    else if (i < 11534336u) { src = wv;  dst = hwv;  off = i - 10485760u; }
    else if (i < 15728640u) { src = wo;  dst = hwo;  off = i - 11534336u; }
    else return;
    float4 v = *(const float4*)(src + off);
    *(__half2*)(dst + off)     = __floats2half2_rn(v.x, v.y);
    *(__half2*)(dst + off + 2) = __floats2half2_rn(v.z, v.w);
}

// ===================== fp16 cp.async GEMM ===================================
// C[M,N] = A[M,K](fp16) @ B[K,N](fp16). BM=BN=128, BK=32, 256 threads
// (8 warps as 4x2, warp tile 32x64), 4-stage cp.async pipeline, 2 CTAs/SM.
// EPI: 0 = fp32 out, 1 = fp32 out * tanh(gate), 2 = fp16 out (smem-staged).
constexpr int BK = 32, STAGES = 4;
constexpr int LDA = 40;    // halves (32 + 8 pad)
constexpr int LDB = 136;   // halves (128 + 8 pad)
constexpr int A_BYTES = 128 * LDA * 2;           // 10240
constexpr int B_BYTES = BK * LDB * 2;            // 8704
constexpr int STAGE_BYTES = A_BYTES + B_BYTES;   // 18944
constexpr int GEMM_SMEM = STAGES * STAGE_BYTES;  // 75776

template <int EPI, typename OutT>
__device__ __forceinline__ void gemm_body(
    const __half* __restrict__ A, const __half* __restrict__ B,
    OutT* __restrict__ C, int N, int K,
    const float* __restrict__ gate, int bx, int by, char* smem) {
    const uint32_t sb = smem_u32(smem);
    const int tid = threadIdx.x;
    const int wid = tid >> 5;
    const int lane = tid & 31;
    const int wm0 = (wid >> 1) * 32;   // 4 warp rows
    const int wn0 = (wid & 1) * 64;    // 2 warp cols
    const int row0 = by * 128;
    const int col0 = bx * 128;
    const int NIT = K / BK;

    const int a_r0 = tid >> 2, a_qb = (tid & 3) * 16;
    const int b_r0 = tid >> 4, b_qb = (tid & 15) * 16;

    auto issue = [&](int it) {
        const int s = it % STAGES;
        const int k0 = it * BK;
        const uint32_t As = sb + s * STAGE_BYTES;
        const uint32_t Bs = As + A_BYTES;
#pragma unroll
        for (int p = 0; p < 2; p++) {
            int r = a_r0 + p * 64;
            cp_async16(As + r * 80 + a_qb,
                       A + (size_t)(row0 + r) * K + k0 + (a_qb >> 1));
        }
#pragma unroll
        for (int p = 0; p < 2; p++) {
            int r = b_r0 + p * 16;
            cp_async16(Bs + r * 272 + b_qb,
                       B + (size_t)(k0 + r) * N + col0 + (b_qb >> 1));
        }
    };

    wmma::fragment<wmma::accumulator, 16, 16, 16, float> acc[2][4];
#pragma unroll
    for (int i = 0; i < 2; i++)
#pragma unroll
        for (int j = 0; j < 4; j++) wmma::fill_fragment(acc[i][j], 0.0f);

#pragma unroll
    for (int s = 0; s < STAGES - 1; s++) {
        issue(s);
        cp_commit();
    }

    for (int it = 0; it < NIT; ++it) {
        cp_wait<STAGES - 2>();
        __syncthreads();

        const int s = it % STAGES;
        const __half* Ah = (const __half*)(smem + s * STAGE_BYTES);
        const __half* Bh = (const __half*)(smem + s * STAGE_BYTES + A_BYTES);

#pragma unroll
        for (int ks = 0; ks < BK / 16; ks++) {
            wmma::fragment<wmma::matrix_a, 16, 16, 16, __half, wmma::row_major> af[2];
            wmma::fragment<wmma::matrix_b, 16, 16, 16, __half, wmma::row_major> bf[4];
#pragma unroll
            for (int i = 0; i < 2; i++)
                wmma::load_matrix_sync(af[i], Ah + (wm0 + i * 16) * LDA + ks * 16, LDA);
#pragma unroll
            for (int j = 0; j < 4; j++)
                wmma::load_matrix_sync(bf[j], Bh + (ks * 16) * LDB + wn0 + j * 16, LDB);
#pragma unroll
            for (int i = 0; i < 2; i++)
#pragma unroll
                for (int j = 0; j < 4; j++)
                    wmma::mma_sync(acc[i][j], af[i], bf[j], acc[i][j]);
        }

        if (it + STAGES - 1 < NIT) issue(it + STAGES - 1);
        cp_commit();
    }

    if (EPI == 2) {
        // fp16 output via per-warp smem staging
        __syncthreads();
        float* scratch = (float*)smem + wid * 256;
        __half* Ch = (__half*)C;
        const int r = lane >> 1, c8 = (lane & 1) * 8;
#pragma unroll
        for (int i = 0; i < 2; i++)
#pragma unroll
            for (int j = 0; j < 4; j++) {
                wmma::store_matrix_sync(scratch, acc[i][j], 16, wmma::mem_row_major);
                __syncwarp();
                float4 v0 = *(float4*)(scratch + r * 16 + c8);
                float4 v1 = *(float4*)(scratch + r * 16 + c8 + 4);
                __half2 h[4];
                h[0] = __floats2half2_rn(v0.x, v0.y);
                h[1] = __floats2half2_rn(v0.z, v0.w);
                h[2] = __floats2half2_rn(v1.x, v1.y);
                h[3] = __floats2half2_rn(v1.z, v1.w);
                *(uint4*)(Ch + (size_t)(row0 + wm0 + i * 16 + r) * N +
                          col0 + wn0 + j * 16 + c8) = *(uint4*)h;
                __syncwarp();
            }
    } else {
        float g = 1.0f;
        if (EPI == 1) g = tanhf(gate[0]);
        float* Cf = (float*)C;
#pragma unroll
        for (int i = 0; i < 2; i++)
#pragma unroll
            for (int j = 0; j < 4; j++) {
                if (EPI == 1) {
#pragma unroll
                    for (int e = 0; e < acc[i][j].num_elements; e++)
                        acc[i][j].x[e] *= g;
                }
                wmma::store_matrix_sync(
                    Cf + (size_t)(row0 + wm0 + i * 16) * N + col0 + wn0 + j * 16,
                    acc[i][j], N, wmma::mem_row_major);
            }
    }
}

// stage 1: fused Q + kproj(fp16) + vproj(fp32). 288 CTAs, 2/SM.
__global__ void __launch_bounds__(256, 2)
fused_gemm1(const __half* __restrict__ hx, const __half* __restrict__ hcst,
            const __half* __restrict__ hwq, const __half* __restrict__ hwk,
            const __half* __restrict__ hwv, float* __restrict__ qb,
            __half* __restrict__ kb, float* __restrict__ vb) {
    extern __shared__ char smem[];
    int bid = blockIdx.x;
    if (bid < 256) {
        gemm_body<0, float>(hx, hwq, qb, 2048, 2048, nullptr, bid & 15, bid >> 4, smem);
    } else {
        int t = bid - 256;            // 0..31
        int w = t >> 4;               // 0: K (fp16 out), 1: V (fp32 out)
        t &= 15;                      // 4x4 tiles of 512x512
        if (w == 0)
            gemm_body<2, __half>(hcst, hwk, kb, 512, 2048, nullptr, t & 3, t >> 2, smem);
        else
            gemm_body<0, float>(hcst, hwv, vb, 512, 2048, nullptr, t & 3, t >> 2, smem);
    }
}

// stage 4: out = (y @ Wo) * tanh(gate). 256 CTAs, 2/SM.
__global__ void __launch_bounds__(256, 2)
out_gemm(const __half* __restrict__ y, const __half* __restrict__ hwo,
         float* __restrict__ out, const float* __restrict__ gate) {
    extern __shared__ char smem[];
    gemm_body<1, float>(y, hwo, out, 2048, 2048, gate, blockIdx.x & 15,
                        blockIdx.x >> 4, smem);
}

// ===================== tiny-K attention (vectorized) ========================
// Block = (token bt, kv-group g), 4 warps = 4 rep heads, lane = key.
// q fp32 -> smem float4; K fp16 -> smem uint4 rows; V fp32 -> smem float4 rows.
__global__ void __launch_bounds__(128)
attn_kernel(const float* __restrict__ q, const __half* __restrict__ kh,
            const float* __restrict__ vproj, const int* __restrict__ mask,
            __half* __restrict__ y) {
    __shared__ float4 qsf[4][32];    // 2 KB  (head-major, broadcast reads)
    __shared__ uint4  ksh[32][17];   // 8.5 KB (row = key, 16 uint4 + pad)
    __shared__ float4 vsf[32][33];   // 16.9 KB (row = key, 32 float4 + pad)

    const int bt = blockIdx.x;
    const int g  = blockIdx.y;
    const int b  = bt >> 10;
    const int tid  = threadIdx.x;
    const int lane = tid & 31;
    const int w    = tid >> 5;

    const int ch = mask[bt];
    const size_t kvbase = ((size_t)(b * 8 + ch) * 32) * 512 + g * 128;

    // q: 512 floats -> 128 float4
    qsf[tid >> 5][tid & 31] =
        *(const float4*)(q + (size_t)bt * 2048 + g * 512 + tid * 4);

    // K fp16: 32 rows x 16 uint4
#pragma unroll
    for (int p = 0; p < 4; p++) {
        int i = tid + p * 128;
        ksh[i >> 4][i & 15] =
            *(const uint4*)(kh + kvbase + (size_t)(i >> 4) * 512 + (i & 15) * 8);
    }
    // V fp32: 32 rows x 32 float4
#pragma unroll
    for (int p = 0; p < 8; p++) {
        int i = tid + p * 128;
        vsf[i >> 5][i & 31] =
            *(const float4*)(vproj + kvbase + (size_t)(i >> 5) * 512 + (i & 31) * 4);
    }
    __syncthreads();

    // score: lane = key, warp = head
    float sc = 0.0f;
#pragma unroll
    for (int c = 0; c < 16; c++) {
        uint4 k4 = ksh[lane][c];
        float4 qa = qsf[w][2 * c];
        float4 qb4 = qsf[w][2 * c + 1];
        const __half2* hp = (const __half2*)&k4;
        float2 f0 = __half22float2(hp[0]);
        float2 f1 = __half22float2(hp[1]);
        float2 f2 = __half22float2(hp[2]);
        float2 f3 = __half22float2(hp[3]);
        sc += f0.x * qa.x + f0.y * qa.y + f1.x * qa.z + f1.y * qa.w;
        sc += f2.x * qb4.x + f2.y * qb4.y + f3.x * qb4.z + f3.y * qb4.w;
    }
    sc *= 0.08838834764831845f;  // 1/sqrt(128)

    float m = sc;
#pragma unroll
    for (int off = 16; off; off >>= 1) m = fmaxf(m, __shfl_xor_sync(0xFFFFFFFFu, m, off));
    float e = __expf(sc - m);
    float s = e;
#pragma unroll
    for (int off = 16; off; off >>= 1) s += __shfl_xor_sync(0xFFFFFFFFu, s, off);
    const float wat = e / s;  // this lane's key weight

    // y: lane owns 4 dims (chunk index = lane)
    float4 acc = make_float4(0.f, 0.f, 0.f, 0.f);
#pragma unroll
    for (int kk = 0; kk < 32; kk++) {
        float a = __shfl_sync(0xFFFFFFFFu, wat, kk);
        float4 v4 = vsf[kk][lane];
        acc.x += a * v4.x; acc.y += a * v4.y;
        acc.z += a * v4.z; acc.w += a * v4.w;
    }
    __half2 h0 = __floats2half2_rn(acc.x, acc.y);
    __half2 h1 = __floats2half2_rn(acc.z, acc.w);
    uint32_t u0, u1;
    memcpy(&u0, &h0, 4);
    memcpy(&u1, &h1, 4);
    uint2 u = make_uint2(u0, u1);
    *(uint2*)(y + (size_t)bt * 2048 + g * 512 + w * 128 + lane * 4) = u;
}

// ===================== launch ===============================================
extern "C" void kernel_launch(void* const* d_in, const int* in_sizes, int n_in,
                              void* d_out, int out_size) {
    const float* x    = (const float*)d_in[0];
    const float* cst  = (const float*)d_in[1];
    const int*   mask = (const int*)d_in[2];
    const float* Wq   = (const float*)d_in[3];
    const float* Wk   = (const float*)d_in[4];
    const float* Wv   = (const float*)d_in[5];
    const float* Wo   = (const float*)d_in[6];
    const float* gate = (const float*)d_in[7];
    float* out = (float*)d_out;

    float *qb, *vb;
    __half *kb, *yb, *hx, *hcst, *hwq, *hwk, *hwv, *hwo;
    cudaGetSymbolAddress((void**)&qb, g_q);
    cudaGetSymbolAddress((void**)&yb, g_y);
    cudaGetSymbolAddress((void**)&kb, g_k);
    cudaGetSymbolAddress((void**)&vb, g_v);
    cudaGetSymbolAddress((void**)&hx, g_hx);
    cudaGetSymbolAddress((void**)&hcst, g_hcst);
    cudaGetSymbolAddress((void**)&hwq, g_hwq);
    cudaGetSymbolAddress((void**)&hwk, g_hwk);
    cudaGetSymbolAddress((void**)&hwv, g_hwv);
    cudaGetSymbolAddress((void**)&hwo, g_hwo);

    cudaFuncSetAttribute(fused_gemm1,
                         cudaFuncAttributeMaxDynamicSharedMemorySize, GEMM_SMEM);
    cudaFuncSetAttribute(out_gemm,
                         cudaFuncAttributeMaxDynamicSharedMemorySize, GEMM_SMEM);

    // 0) convert all GEMM inputs to fp16
    cvt_all<<<15360, 256>>>(x, cst, Wq, Wk, Wv, Wo, hx, hcst, hwq, hwk, hwv, hwo);
    // 1+2) Q projection + kproj(fp16) + vproj(fp32)
    fused_gemm1<<<288, 256, GEMM_SMEM>>>(hx, hcst, hwq, hwk, hwv, qb, kb, vb);
    // 3) gather + tiny-K GQA attention (y in fp16)
    attn_kernel<<<dim3(2048, 4), 128>>>(qb, kb, vb, mask, yb);
    // 4) out = (y @ Wo) * tanh(gate)
    out_gemm<<<256, 256, GEMM_SMEM>>>(yb, hwo, out, gate);
}

// round 8
// speedup vs baseline: 9.7942x; 1.0238x over previous
#include <cuda_runtime.h>
#include <cuda_fp16.h>
#include <math.h>
#include <stdint.h>
#include <mma.h>

using namespace nvcuda;

// ===================== static scratch (no allocs allowed) ====================
__device__ __half g_q[2048 * 2048];    // Q projection (fp16)
__device__ __half g_y[2048 * 2048];    // attention out (fp16)
__device__ __half g_k[512 * 512];      // kproj fp16
__device__ __half g_v[512 * 512];      // vproj fp16
__device__ __half g_hx[2048 * 2048];   // x   in fp16
__device__ __half g_hcst[512 * 2048];  // cst in fp16
__device__ __half g_hwq[2048 * 2048];
__device__ __half g_hwk[2048 * 512];
__device__ __half g_hwv[2048 * 512];
__device__ __half g_hwo[2048 * 2048];

__device__ __forceinline__ uint32_t smem_u32(const void* p) {
    uint32_t a;
    asm("{ .reg .u64 t; cvta.to.shared.u64 t, %1; cvt.u32.u64 %0, t; }"
        : "=r"(a) : "l"(p));
    return a;
}
__device__ __forceinline__ void cp_async16(uint32_t dst, const void* src) {
    asm volatile("cp.async.cg.shared.global [%0], [%1], 16;" :: "r"(dst), "l"(src));
}
__device__ __forceinline__ void cp_commit() {
    asm volatile("cp.async.commit_group;" ::: "memory");
}
template <int N>
__device__ __forceinline__ void cp_wait() {
    asm volatile("cp.async.wait_group %0;" :: "n"(N) : "memory");
}

// ===================== fp32 -> fp16 conversion (all GEMM inputs) ============
__global__ void __launch_bounds__(256)
cvt_all(const float* __restrict__ x, const float* __restrict__ cst,
        const float* __restrict__ wq, const float* __restrict__ wk,
        const float* __restrict__ wv, const float* __restrict__ wo,
        __half* __restrict__ hx, __half* __restrict__ hcst,
        __half* __restrict__ hwq, __half* __restrict__ hwk,
        __half* __restrict__ hwv, __half* __restrict__ hwo) {
    size_t i = ((size_t)blockIdx.x * blockDim.x + threadIdx.x) * 4;
    const float* src; __half* dst; size_t off;
    if      (i <  4194304u) { src = x;   dst = hx;   off = i; }
    else if (i <  5242880u) { src = cst; dst = hcst; off = i - 4194304u; }
    else if (i <  9437184u) { src = wq;  dst = hwq;  off = i - 5242880u; }
    else if (i < 10485760u) { src = wk;  dst = hwk;  off = i - 9437184u; }
    else if (i < 11534336u) { src = wv;  dst = hwv;  off = i - 10485760u; }
    else if (i < 15728640u) { src = wo;  dst = hwo;  off = i - 11534336u; }
    else return;
    float4 v = *(const float4*)(src + off);
    *(__half2*)(dst + off)     = __floats2half2_rn(v.x, v.y);
    *(__half2*)(dst + off + 2) = __floats2half2_rn(v.z, v.w);
}

// ===================== fp16 cp.async GEMM ===================================
// C[M,N] = A[M,K](fp16) @ B[K,N](fp16). BM=BN=128, BK=32, 256 threads
// (8 warps as 4x2, warp tile 32x64), 5-stage cp.async pipeline, 2 CTAs/SM.
// EPI: 0 = fp32 out, 1 = fp32 out * tanh(gate), 2 = fp16 out (smem-staged).
constexpr int BK = 32, STAGES = 5;
constexpr int LDA = 40;    // halves (32 + 8 pad)
constexpr int LDB = 136;   // halves (128 + 8 pad)
constexpr int A_BYTES = 128 * LDA * 2;           // 10240
constexpr int B_BYTES = BK * LDB * 2;            // 8704
constexpr int STAGE_BYTES = A_BYTES + B_BYTES;   // 18944
constexpr int GEMM_SMEM = STAGES * STAGE_BYTES;  // 94720

template <int EPI, typename OutT>
__device__ __forceinline__ void gemm_body(
    const __half* __restrict__ A, const __half* __restrict__ B,
    OutT* __restrict__ C, int N, int K,
    const float* __restrict__ gate, int bx, int by, char* smem) {
    const uint32_t sb = smem_u32(smem);
    const int tid = threadIdx.x;
    const int wid = tid >> 5;
    const int lane = tid & 31;
    const int wm0 = (wid >> 1) * 32;   // 4 warp rows
    const int wn0 = (wid & 1) * 64;    // 2 warp cols
    const int row0 = by * 128;
    const int col0 = bx * 128;
    const int NIT = K / BK;

    const int a_r0 = tid >> 2, a_qb = (tid & 3) * 16;
    const int b_r0 = tid >> 4, b_qb = (tid & 15) * 16;

    auto issue = [&](int it) {
        const int s = it % STAGES;
        const int k0 = it * BK;
        const uint32_t As = sb + s * STAGE_BYTES;
        const uint32_t Bs = As + A_BYTES;
#pragma unroll
        for (int p = 0; p < 2; p++) {
            int r = a_r0 + p * 64;
            cp_async16(As + r * 80 + a_qb,
                       A + (size_t)(row0 + r) * K + k0 + (a_qb >> 1));
        }
#pragma unroll
        for (int p = 0; p < 2; p++) {
            int r = b_r0 + p * 16;
            cp_async16(Bs + r * 272 + b_qb,
                       B + (size_t)(k0 + r) * N + col0 + (b_qb >> 1));
        }
    };

    wmma::fragment<wmma::accumulator, 16, 16, 16, float> acc[2][4];
#pragma unroll
    for (int i = 0; i < 2; i++)
#pragma unroll
        for (int j = 0; j < 4; j++) wmma::fill_fragment(acc[i][j], 0.0f);

#pragma unroll
    for (int s = 0; s < STAGES - 1; s++) {
        issue(s);
        cp_commit();
    }

    for (int it = 0; it < NIT; ++it) {
        cp_wait<STAGES - 2>();
        __syncthreads();

        const int s = it % STAGES;
        const __half* Ah = (const __half*)(smem + s * STAGE_BYTES);
        const __half* Bh = (const __half*)(smem + s * STAGE_BYTES + A_BYTES);

#pragma unroll
        for (int ks = 0; ks < BK / 16; ks++) {
            wmma::fragment<wmma::matrix_a, 16, 16, 16, __half, wmma::row_major> af[2];
            wmma::fragment<wmma::matrix_b, 16, 16, 16, __half, wmma::row_major> bf[4];
#pragma unroll
            for (int i = 0; i < 2; i++)
                wmma::load_matrix_sync(af[i], Ah + (wm0 + i * 16) * LDA + ks * 16, LDA);
#pragma unroll
            for (int j = 0; j < 4; j++)
                wmma::load_matrix_sync(bf[j], Bh + (ks * 16) * LDB + wn0 + j * 16, LDB);
#pragma unroll
            for (int i = 0; i < 2; i++)
#pragma unroll
                for (int j = 0; j < 4; j++)
                    wmma::mma_sync(acc[i][j], af[i], bf[j], acc[i][j]);
        }

        if (it + STAGES - 1 < NIT) issue(it + STAGES - 1);
        cp_commit();
    }

    if (EPI == 2) {
        // fp16 output via per-warp smem staging
        __syncthreads();
        float* scratch = (float*)smem + wid * 256;
        __half* Ch = (__half*)C;
        const int r = lane >> 1, c8 = (lane & 1) * 8;
#pragma unroll
        for (int i = 0; i < 2; i++)
#pragma unroll
            for (int j = 0; j < 4; j++) {
                wmma::store_matrix_sync(scratch, acc[i][j], 16, wmma::mem_row_major);
                __syncwarp();
                float4 v0 = *(float4*)(scratch + r * 16 + c8);
                float4 v1 = *(float4*)(scratch + r * 16 + c8 + 4);
                __half2 h[4];
                h[0] = __floats2half2_rn(v0.x, v0.y);
                h[1] = __floats2half2_rn(v0.z, v0.w);
                h[2] = __floats2half2_rn(v1.x, v1.y);
                h[3] = __floats2half2_rn(v1.z, v1.w);
                *(uint4*)(Ch + (size_t)(row0 + wm0 + i * 16 + r) * N +
                          col0 + wn0 + j * 16 + c8) = *(uint4*)h;
                __syncwarp();
            }
    } else {
        float g = 1.0f;
        if (EPI == 1) g = tanhf(gate[0]);
        float* Cf = (float*)C;
#pragma unroll
        for (int i = 0; i < 2; i++)
#pragma unroll
            for (int j = 0; j < 4; j++) {
                if (EPI == 1) {
#pragma unroll
                    for (int e = 0; e < acc[i][j].num_elements; e++)
                        acc[i][j].x[e] *= g;
                }
                wmma::store_matrix_sync(
                    Cf + (size_t)(row0 + wm0 + i * 16) * N + col0 + wn0 + j * 16,
                    acc[i][j], N, wmma::mem_row_major);
            }
    }
}

// stage 1: fused Q(fp16) + kproj(fp16) + vproj(fp16). 288 CTAs, 2/SM.
__global__ void __launch_bounds__(256, 2)
fused_gemm1(const __half* __restrict__ hx, const __half* __restrict__ hcst,
            const __half* __restrict__ hwq, const __half* __restrict__ hwk,
            const __half* __restrict__ hwv, __half* __restrict__ qb,
            __half* __restrict__ kb, __half* __restrict__ vb) {
    extern __shared__ char smem[];
    int bid = blockIdx.x;
    if (bid < 256) {
        gemm_body<2, __half>(hx, hwq, qb, 2048, 2048, nullptr, bid & 15, bid >> 4, smem);
    } else {
        int t = bid - 256;            // 0..31
        int w = t >> 4;               // 0: K, 1: V
        t &= 15;                      // 4x4 tiles of 512x512
        gemm_body<2, __half>(hcst, w ? hwv : hwk, w ? vb : kb, 512, 2048,
                             nullptr, t & 3, t >> 2, smem);
    }
}

// stage 4: out = (y @ Wo) * tanh(gate). 256 CTAs, 2/SM.
__global__ void __launch_bounds__(256, 2)
out_gemm(const __half* __restrict__ y, const __half* __restrict__ hwo,
         float* __restrict__ out, const float* __restrict__ gate) {
    extern __shared__ char smem[];
    gemm_body<1, float>(y, hwo, out, 2048, 2048, gate, blockIdx.x & 15,
                        blockIdx.x >> 4, smem);
}

// ===================== tiny-K attention (all fp16 storage) ==================
// Block = (token bt, kv-group g), 4 warps = 4 rep heads, lane = key.
// fp32 accumulate throughout; only storage is fp16.
__global__ void __launch_bounds__(128)
attn_kernel(const __half* __restrict__ qh, const __half* __restrict__ kh,
            const __half* __restrict__ vh, const int* __restrict__ mask,
            __half* __restrict__ y) {
    __shared__ uint4 qsh[4][17];     // 4 heads x 128 halves (+pad)
    __shared__ uint4 ksh[32][17];    // 32 keys x 128 halves (+pad)
    __shared__ uint4 vsh[32][17];

    const int bt = blockIdx.x;
    const int g  = blockIdx.y;
    const int b  = bt >> 10;
    const int tid  = threadIdx.x;
    const int lane = tid & 31;
    const int w    = tid >> 5;

    const int ch = mask[bt];
    const size_t kvbase = ((size_t)(b * 8 + ch) * 32) * 512 + g * 128;

    // q: 512 halves = 64 uint4
    if (tid < 64)
        qsh[tid >> 4][tid & 15] =
            *(const uint4*)(qh + (size_t)bt * 2048 + g * 512 + tid * 8);
    // K, V: 32 rows x 16 uint4 each
#pragma unroll
    for (int p = 0; p < 4; p++) {
        int i = tid + p * 128;
        ksh[i >> 4][i & 15] =
            *(const uint4*)(kh + kvbase + (size_t)(i >> 4) * 512 + (i & 15) * 8);
        vsh[i >> 4][i & 15] =
            *(const uint4*)(vh + kvbase + (size_t)(i >> 4) * 512 + (i & 15) * 8);
    }
    __syncthreads();

    // score: lane = key, warp = head
    float sc = 0.0f;
#pragma unroll
    for (int c = 0; c < 16; c++) {
        uint4 k4 = qsh[w][c];       // broadcast
        uint4 kk4 = ksh[lane][c];
        const __half2* qp = (const __half2*)&k4;
        const __half2* kp = (const __half2*)&kk4;
#pragma unroll
        for (int u = 0; u < 4; u++) {
            float2 qf = __half22float2(qp[u]);
            float2 kf = __half22float2(kp[u]);
            sc += qf.x * kf.x + qf.y * kf.y;
        }
    }
    sc *= 0.08838834764831845f;  // 1/sqrt(128)

    float m = sc;
#pragma unroll
    for (int off = 16; off; off >>= 1) m = fmaxf(m, __shfl_xor_sync(0xFFFFFFFFu, m, off));
    float e = __expf(sc - m);
    float s = e;
#pragma unroll
    for (int off = 16; off; off >>= 1) s += __shfl_xor_sync(0xFFFFFFFFu, s, off);
    const float wat = e / s;  // this lane's key weight

    // AV: lane owns 4 dims (halves [lane*4, lane*4+4))
    float4 acc = make_float4(0.f, 0.f, 0.f, 0.f);
#pragma unroll
    for (int kk = 0; kk < 32; kk++) {
        float a = __shfl_sync(0xFFFFFFFFu, wat, kk);
        uint2 v2 = *((const uint2*)&vsh[kk][0] + lane);
        float2 f0 = __half22float2(*(const __half2*)&v2.x);
        float2 f1 = __half22float2(*(const __half2*)&v2.y);
        acc.x += a * f0.x; acc.y += a * f0.y;
        acc.z += a * f1.x; acc.w += a * f1.y;
    }
    __half2 h0 = __floats2half2_rn(acc.x, acc.y);
    __half2 h1 = __floats2half2_rn(acc.z, acc.w);
    uint32_t u0, u1;
    memcpy(&u0, &h0, 4);
    memcpy(&u1, &h1, 4);
    *(uint2*)(y + (size_t)bt * 2048 + g * 512 + w * 128 + lane * 4) =
        make_uint2(u0, u1);
}

// ===================== launch ===============================================
extern "C" void kernel_launch(void* const* d_in, const int* in_sizes, int n_in,
                              void* d_out, int out_size) {
    const float* x    = (const float*)d_in[0];
    const float* cst  = (const float*)d_in[1];
    const int*   mask = (const int*)d_in[2];
    const float* Wq   = (const float*)d_in[3];
    const float* Wk   = (const float*)d_in[4];
    const float* Wv   = (const float*)d_in[5];
    const float* Wo   = (const float*)d_in[6];
    const float* gate = (const float*)d_in[7];
    float* out = (float*)d_out;

    __half *qb, *kb, *vb, *yb, *hx, *hcst, *hwq, *hwk, *hwv, *hwo;
    cudaGetSymbolAddress((void**)&qb, g_q);
    cudaGetSymbolAddress((void**)&yb, g_y);
    cudaGetSymbolAddress((void**)&kb, g_k);
    cudaGetSymbolAddress((void**)&vb, g_v);
    cudaGetSymbolAddress((void**)&hx, g_hx);
    cudaGetSymbolAddress((void**)&hcst, g_hcst);
    cudaGetSymbolAddress((void**)&hwq, g_hwq);
    cudaGetSymbolAddress((void**)&hwk, g_hwk);
    cudaGetSymbolAddress((void**)&hwv, g_hwv);
    cudaGetSymbolAddress((void**)&hwo, g_hwo);

    cudaFuncSetAttribute(fused_gemm1,
                         cudaFuncAttributeMaxDynamicSharedMemorySize, GEMM_SMEM);
    cudaFuncSetAttribute(out_gemm,
                         cudaFuncAttributeMaxDynamicSharedMemorySize, GEMM_SMEM);

    // 0) convert all GEMM inputs to fp16
    cvt_all<<<15360, 256>>>(x, cst, Wq, Wk, Wv, Wo, hx, hcst, hwq, hwk, hwv, hwo);
    // 1+2) Q + kproj + vproj, all fp16 outputs
    fused_gemm1<<<288, 256, GEMM_SMEM>>>(hx, hcst, hwq, hwk, hwv, qb, kb, vb);
    // 3) gather + tiny-K GQA attention (fp16 in/out, fp32 accumulate)
    attn_kernel<<<dim3(2048, 4), 128>>>(qb, kb, vb, mask, yb);
    // 4) out = (y @ Wo) * tanh(gate)
    out_gemm<<<256, 256, GEMM_SMEM>>>(yb, hwo, out, gate);
}

// round 9
// speedup vs baseline: 10.2556x; 1.0471x over previous
#include <cuda_runtime.h>
#include <cuda_fp16.h>
#include <math.h>
#include <stdint.h>
#include <mma.h>

using namespace nvcuda;

// ===================== static scratch (no allocs allowed) ====================
__device__ __half g_q[2048 * 2048];    // Q projection (fp16)
__device__ __half g_y[2048 * 2048];    // attention out (fp16)
__device__ __half g_k[512 * 512];      // kproj fp16
__device__ __half g_v[512 * 512];      // vproj fp16
__device__ __half g_hx[2048 * 2048];   // x   in fp16
__device__ __half g_hcst[512 * 2048];  // cst in fp16
__device__ __half g_hwq[2048 * 2048];
__device__ __half g_hwk[2048 * 512];
__device__ __half g_hwv[2048 * 512];
__device__ __half g_hwo[2048 * 2048];

__device__ __forceinline__ uint32_t smem_u32(const void* p) {
    uint32_t a;
    asm("{ .reg .u64 t; cvta.to.shared.u64 t, %1; cvt.u32.u64 %0, t; }"
        : "=r"(a) : "l"(p));
    return a;
}
__device__ __forceinline__ void cp_async16(uint32_t dst, const void* src) {
    asm volatile("cp.async.cg.shared.global [%0], [%1], 16;" :: "r"(dst), "l"(src));
}
__device__ __forceinline__ void cp_commit() {
    asm volatile("cp.async.commit_group;" ::: "memory");
}
template <int N>
__device__ __forceinline__ void cp_wait() {
    asm volatile("cp.async.wait_group %0;" :: "n"(N) : "memory");
}

// ===================== fp32 -> fp16 conversion (all GEMM inputs) ============
__global__ void __launch_bounds__(256)
cvt_all(const float* __restrict__ x, const float* __restrict__ cst,
        const float* __restrict__ wq, const float* __restrict__ wk,
        const float* __restrict__ wv, const float* __restrict__ wo,
        __half* __restrict__ hx, __half* __restrict__ hcst,
        __half* __restrict__ hwq, __half* __restrict__ hwk,
        __half* __restrict__ hwv, __half* __restrict__ hwo) {
    size_t i = ((size_t)blockIdx.x * blockDim.x + threadIdx.x) * 4;
    const float* src; __half* dst; size_t off;
    if      (i <  4194304u) { src = x;   dst = hx;   off = i; }
    else if (i <  5242880u) { src = cst; dst = hcst; off = i - 4194304u; }
    else if (i <  9437184u) { src = wq;  dst = hwq;  off = i - 5242880u; }
    else if (i < 10485760u) { src = wk;  dst = hwk;  off = i - 9437184u; }
    else if (i < 11534336u) { src = wv;  dst = hwv;  off = i - 10485760u; }
    else if (i < 15728640u) { src = wo;  dst = hwo;  off = i - 11534336u; }
    else return;
    float4 v = *(const float4*)(src + off);
    *(__half2*)(dst + off)     = __floats2half2_rn(v.x, v.y);
    *(__half2*)(dst + off + 2) = __floats2half2_rn(v.z, v.w);
}

// ===================== fp16 cp.async GEMM ===================================
// C[M,N] = A[M,K](fp16) @ B[K,N](fp16). BM=BN=128, BK=64, 256 threads
// (8 warps as 4x2, warp tile 32x64), 3-stage cp.async pipeline, 2 CTAs/SM.
// EPI: 1 = fp32 out * tanh(gate), 2 = fp16 out (smem-staged).
constexpr int BK = 64, STAGES = 3;
constexpr int LDA = 72;    // halves (64 + 8 pad) -> 144B pitch
constexpr int LDB = 136;   // halves (128 + 8 pad) -> 272B pitch
constexpr int A_BYTES = 128 * LDA * 2;           // 18432
constexpr int B_BYTES = BK * LDB * 2;            // 17408
constexpr int STAGE_BYTES = A_BYTES + B_BYTES;   // 35840
constexpr int GEMM_SMEM = STAGES * STAGE_BYTES;  // 107520

template <int EPI, typename OutT>
__device__ __forceinline__ void gemm_body(
    const __half* __restrict__ A, const __half* __restrict__ B,
    OutT* __restrict__ C, int N, int K,
    const float* __restrict__ gate, int bx, int by, char* smem) {
    const uint32_t sb = smem_u32(smem);
    const int tid = threadIdx.x;
    const int wid = tid >> 5;
    const int lane = tid & 31;
    const int wm0 = (wid >> 1) * 32;   // 4 warp rows
    const int wn0 = (wid & 1) * 64;    // 2 warp cols
    const int row0 = by * 128;
    const int col0 = bx * 128;
    const int NIT = K / BK;

    // A: 128 rows x 128B -> 1024 chunks, 4/thread (32 rows per pass)
    const int a_r0 = tid >> 3, a_qb = (tid & 7) * 16;
    // B: 64 rows x 256B -> 1024 chunks, 4/thread (16 rows per pass)
    const int b_r0 = tid >> 4, b_qb = (tid & 15) * 16;

    auto issue = [&](int it) {
        const int s = it % STAGES;
        const int k0 = it * BK;
        const uint32_t As = sb + s * STAGE_BYTES;
        const uint32_t Bs = As + A_BYTES;
#pragma unroll
        for (int p = 0; p < 4; p++) {
            int r = a_r0 + p * 32;
            cp_async16(As + r * 144 + a_qb,
                       A + (size_t)(row0 + r) * K + k0 + (a_qb >> 1));
        }
#pragma unroll
        for (int p = 0; p < 4; p++) {
            int r = b_r0 + p * 16;
            cp_async16(Bs + r * 272 + b_qb,
                       B + (size_t)(k0 + r) * N + col0 + (b_qb >> 1));
        }
    };

    wmma::fragment<wmma::accumulator, 16, 16, 16, float> acc[2][4];
#pragma unroll
    for (int i = 0; i < 2; i++)
#pragma unroll
        for (int j = 0; j < 4; j++) wmma::fill_fragment(acc[i][j], 0.0f);

#pragma unroll
    for (int s = 0; s < STAGES - 1; s++) {
        issue(s);
        cp_commit();
    }

    for (int it = 0; it < NIT; ++it) {
        cp_wait<STAGES - 2>();
        __syncthreads();

        const int s = it % STAGES;
        const __half* Ah = (const __half*)(smem + s * STAGE_BYTES);
        const __half* Bh = (const __half*)(smem + s * STAGE_BYTES + A_BYTES);

#pragma unroll
        for (int ks = 0; ks < BK / 16; ks++) {
            wmma::fragment<wmma::matrix_a, 16, 16, 16, __half, wmma::row_major> af[2];
            wmma::fragment<wmma::matrix_b, 16, 16, 16, __half, wmma::row_major> bf[4];
#pragma unroll
            for (int i = 0; i < 2; i++)
                wmma::load_matrix_sync(af[i], Ah + (wm0 + i * 16) * LDA + ks * 16, LDA);
#pragma unroll
            for (int j = 0; j < 4; j++)
                wmma::load_matrix_sync(bf[j], Bh + (ks * 16) * LDB + wn0 + j * 16, LDB);
#pragma unroll
            for (int i = 0; i < 2; i++)
#pragma unroll
                for (int j = 0; j < 4; j++)
                    wmma::mma_sync(acc[i][j], af[i], bf[j], acc[i][j]);
        }

        if (it + STAGES - 1 < NIT) issue(it + STAGES - 1);
        cp_commit();
    }

    if (EPI == 2) {
        // fp16 output via per-warp smem staging
        __syncthreads();
        float* scratch = (float*)smem + wid * 256;
        __half* Ch = (__half*)C;
        const int r = lane >> 1, c8 = (lane & 1) * 8;
#pragma unroll
        for (int i = 0; i < 2; i++)
#pragma unroll
            for (int j = 0; j < 4; j++) {
                wmma::store_matrix_sync(scratch, acc[i][j], 16, wmma::mem_row_major);
                __syncwarp();
                float4 v0 = *(float4*)(scratch + r * 16 + c8);
                float4 v1 = *(float4*)(scratch + r * 16 + c8 + 4);
                __half2 h[4];
                h[0] = __floats2half2_rn(v0.x, v0.y);
                h[1] = __floats2half2_rn(v0.z, v0.w);
                h[2] = __floats2half2_rn(v1.x, v1.y);
                h[3] = __floats2half2_rn(v1.z, v1.w);
                *(uint4*)(Ch + (size_t)(row0 + wm0 + i * 16 + r) * N +
                          col0 + wn0 + j * 16 + c8) = *(uint4*)h;
                __syncwarp();
            }
    } else {
        float g = tanhf(gate[0]);
        float* Cf = (float*)C;
#pragma unroll
        for (int i = 0; i < 2; i++)
#pragma unroll
            for (int j = 0; j < 4; j++) {
#pragma unroll
                for (int e = 0; e < acc[i][j].num_elements; e++)
                    acc[i][j].x[e] *= g;
                wmma::store_matrix_sync(
                    Cf + (size_t)(row0 + wm0 + i * 16) * N + col0 + wn0 + j * 16,
                    acc[i][j], N, wmma::mem_row_major);
            }
    }
}

// stage 1: fused Q(fp16) + kproj(fp16) + vproj(fp16). 288 CTAs, 2/SM.
__global__ void __launch_bounds__(256, 2)
fused_gemm1(const __half* __restrict__ hx, const __half* __restrict__ hcst,
            const __half* __restrict__ hwq, const __half* __restrict__ hwk,
            const __half* __restrict__ hwv, __half* __restrict__ qb,
            __half* __restrict__ kb, __half* __restrict__ vb) {
    extern __shared__ char smem[];
    int bid = blockIdx.x;
    if (bid < 256) {
        gemm_body<2, __half>(hx, hwq, qb, 2048, 2048, nullptr, bid & 15, bid >> 4, smem);
    } else {
        int t = bid - 256;            // 0..31
        int w = t >> 4;               // 0: K, 1: V
        t &= 15;                      // 4x4 tiles of 512x512
        gemm_body<2, __half>(hcst, w ? hwv : hwk, w ? vb : kb, 512, 2048,
                             nullptr, t & 3, t >> 2, smem);
    }
}

// stage 4: out = (y @ Wo) * tanh(gate). 256 CTAs, 2/SM.
__global__ void __launch_bounds__(256, 2)
out_gemm(const __half* __restrict__ y, const __half* __restrict__ hwo,
         float* __restrict__ out, const float* __restrict__ gate) {
    extern __shared__ char smem[];
    gemm_body<1, float>(y, hwo, out, 2048, 2048, gate, blockIdx.x & 15,
                        blockIdx.x >> 4, smem);
}

// ===================== tiny-K attention (all fp16 storage) ==================
__global__ void __launch_bounds__(128)
attn_kernel(const __half* __restrict__ qh, const __half* __restrict__ kh,
            const __half* __restrict__ vh, const int* __restrict__ mask,
            __half* __restrict__ y) {
    __shared__ uint4 qsh[4][17];     // 4 heads x 128 halves (+pad)
    __shared__ uint4 ksh[32][17];    // 32 keys x 128 halves (+pad)
    __shared__ uint4 vsh[32][17];

    const int bt = blockIdx.x;
    const int g  = blockIdx.y;
    const int b  = bt >> 10;
    const int tid  = threadIdx.x;
    const int lane = tid & 31;
    const int w    = tid >> 5;

    const int ch = mask[bt];
    const size_t kvbase = ((size_t)(b * 8 + ch) * 32) * 512 + g * 128;

    if (tid < 64)
        qsh[tid >> 4][tid & 15] =
            *(const uint4*)(qh + (size_t)bt * 2048 + g * 512 + tid * 8);
#pragma unroll
    for (int p = 0; p < 4; p++) {
        int i = tid + p * 128;
        ksh[i >> 4][i & 15] =
            *(const uint4*)(kh + kvbase + (size_t)(i >> 4) * 512 + (i & 15) * 8);
        vsh[i >> 4][i & 15] =
            *(const uint4*)(vh + kvbase + (size_t)(i >> 4) * 512 + (i & 15) * 8);
    }
    __syncthreads();

    float sc = 0.0f;
#pragma unroll
    for (int c = 0; c < 16; c++) {
        uint4 k4 = qsh[w][c];       // broadcast
        uint4 kk4 = ksh[lane][c];
        const __half2* qp = (const __half2*)&k4;
        const __half2* kp = (const __half2*)&kk4;
#pragma unroll
        for (int u = 0; u < 4; u++) {
            float2 qf = __half22float2(qp[u]);
            float2 kf = __half22float2(kp[u]);
            sc += qf.x * kf.x + qf.y * kf.y;
        }
    }
    sc *= 0.08838834764831845f;  // 1/sqrt(128)

    float m = sc;
#pragma unroll
    for (int off = 16; off; off >>= 1) m = fmaxf(m, __shfl_xor_sync(0xFFFFFFFFu, m, off));
    float e = __expf(sc - m);
    float s = e;
#pragma unroll
    for (int off = 16; off; off >>= 1) s += __shfl_xor_sync(0xFFFFFFFFu, s, off);
    const float wat = e / s;

    float4 acc = make_float4(0.f, 0.f, 0.f, 0.f);
#pragma unroll
    for (int kk = 0; kk < 32; kk++) {
        float a = __shfl_sync(0xFFFFFFFFu, wat, kk);
        uint2 v2 = *((const uint2*)&vsh[kk][0] + lane);
        float2 f0 = __half22float2(*(const __half2*)&v2.x);
        float2 f1 = __half22float2(*(const __half2*)&v2.y);
        acc.x += a * f0.x; acc.y += a * f0.y;
        acc.z += a * f1.x; acc.w += a * f1.y;
    }
    __half2 h0 = __floats2half2_rn(acc.x, acc.y);
    __half2 h1 = __floats2half2_rn(acc.z, acc.w);
    uint32_t u0, u1;
    memcpy(&u0, &h0, 4);
    memcpy(&u1, &h1, 4);
    *(uint2*)(y + (size_t)bt * 2048 + g * 512 + w * 128 + lane * 4) =
        make_uint2(u0, u1);
}

// ===================== launch ===============================================
extern "C" void kernel_launch(void* const* d_in, const int* in_sizes, int n_in,
                              void* d_out, int out_size) {
    const float* x    = (const float*)d_in[0];
    const float* cst  = (const float*)d_in[1];
    const int*   mask = (const int*)d_in[2];
    const float* Wq   = (const float*)d_in[3];
    const float* Wk   = (const float*)d_in[4];
    const float* Wv   = (const float*)d_in[5];
    const float* Wo   = (const float*)d_in[6];
    const float* gate = (const float*)d_in[7];
    float* out = (float*)d_out;

    __half *qb, *kb, *vb, *yb, *hx, *hcst, *hwq, *hwk, *hwv, *hwo;
    cudaGetSymbolAddress((void**)&qb, g_q);
    cudaGetSymbolAddress((void**)&yb, g_y);
    cudaGetSymbolAddress((void**)&kb, g_k);
    cudaGetSymbolAddress((void**)&vb, g_v);
    cudaGetSymbolAddress((void**)&hx, g_hx);
    cudaGetSymbolAddress((void**)&hcst, g_hcst);
    cudaGetSymbolAddress((void**)&hwq, g_hwq);
    cudaGetSymbolAddress((void**)&hwk, g_hwk);
    cudaGetSymbolAddress((void**)&hwv, g_hwv);
    cudaGetSymbolAddress((void**)&hwo, g_hwo);

    cudaFuncSetAttribute(fused_gemm1,
                         cudaFuncAttributeMaxDynamicSharedMemorySize, GEMM_SMEM);
    cudaFuncSetAttribute(out_gemm,
                         cudaFuncAttributeMaxDynamicSharedMemorySize, GEMM_SMEM);

    // 0) convert all GEMM inputs to fp16
    cvt_all<<<15360, 256>>>(x, cst, Wq, Wk, Wv, Wo, hx, hcst, hwq, hwk, hwv, hwo);
    // 1+2) Q + kproj + vproj, all fp16 outputs
    fused_gemm1<<<288, 256, GEMM_SMEM>>>(hx, hcst, hwq, hwk, hwv, qb, kb, vb);
    // 3) gather + tiny-K GQA attention (fp16 in/out, fp32 accumulate)
    attn_kernel<<<dim3(2048, 4), 128>>>(qb, kb, vb, mask, yb);
    // 4) out = (y @ Wo) * tanh(gate)
    out_gemm<<<256, 256, GEMM_SMEM>>>(yb, hwo, out, gate);
}